// round 1
// baseline (speedup 1.0000x reference)
#include <cuda_runtime.h>
#include <math.h>

#define NN 32
#define CC 64
#define TT 512
#define VV 25
#define C4V 16
#define W3V 75
#define COV 64
#define KSPLIT 8
#define KTOT (C4V*TT)        /* 8192 */
#define KCHUNK (KTOT/KSPLIT) /* 1024 */
#define TPB 4

// -------- device scratch (static; no runtime allocation) --------
__device__ float g_B[NN*C4V*TT*VV];          // conv_a(x) without bias: 6.55M floats
__device__ float g_Gpart[NN*KSPLIT*W3V*W3V]; // Gram partials
__device__ float g_att[NN*W3V*W3V];          // softmax(att)

// ============================================================
// K1: B[n,o,t,v] = sum_c conv_a_w[o,c] * x[n,c,t,v]
// per-n GEMM M=16, K=64, N'=T*V=12800 (plane is contiguous)
// ============================================================
__global__ void k1_convA(const float* __restrict__ x, const float* __restrict__ Wa)
{
    __shared__ float sW[C4V*CC];
    int tid = threadIdx.x;
    for (int i = tid; i < C4V*CC; i += blockDim.x) sW[i] = Wa[i];
    __syncthreads();

    int n  = blockIdx.y;
    int j0 = (blockIdx.x * blockDim.x + tid) * 4;
    if (j0 >= TT*VV) return;

    const float* xp = x + (size_t)n*CC*TT*VV + j0;
    float acc[C4V][4];
#pragma unroll
    for (int o = 0; o < C4V; o++) { acc[o][0]=acc[o][1]=acc[o][2]=acc[o][3]=0.f; }

#pragma unroll 4
    for (int c = 0; c < CC; c++) {
        float4 xv = *reinterpret_cast<const float4*>(xp + (size_t)c*TT*VV);
#pragma unroll
        for (int o = 0; o < C4V; o++) {
            float w = sW[o*CC + c];
            acc[o][0] += w*xv.x; acc[o][1] += w*xv.y;
            acc[o][2] += w*xv.z; acc[o][3] += w*xv.w;
        }
    }
    float* bp = g_B + (size_t)n*C4V*TT*VV + j0;
#pragma unroll
    for (int o = 0; o < C4V; o++) {
        float4 r = make_float4(acc[o][0], acc[o][1], acc[o][2], acc[o][3]);
        *reinterpret_cast<float4*>(bp + (size_t)o*TT*VV) = r;
    }
}

// ============================================================
// K2: Gram partials G[n][w1][w2] = sum_{k in chunk} a1[k][w1]*a1[k][w2]
// a1[k=(o,t)][w=(win,v)] = (in-range ? B[n,o,t+win-1,v] : 0) + conv_a_b[o]
// block = (ks, n); 225 threads compute 5x5 register tiles
// ============================================================
__global__ void k2_gram(const float* __restrict__ ba)
{
    __shared__ float tile[32][W3V + 1];
    int n  = blockIdx.y;
    int ks = blockIdx.x;
    int tid = threadIdx.x;
    int tw1 = tid / 15, tw2 = tid % 15;

    float acc[5][5];
#pragma unroll
    for (int i = 0; i < 5; i++)
#pragma unroll
        for (int j = 0; j < 5; j++) acc[i][j] = 0.f;

    int k0 = ks * KCHUNK;
    for (int kt = 0; kt < KCHUNK; kt += 32) {
        for (int i = tid; i < 32*W3V; i += blockDim.x) {
            int r = i / W3V, w = i - r*W3V;
            int k = k0 + kt + r;
            int o = k >> 9, t = k & 511;
            int win = w / VV, v = w - win*VV;
            int ts = t + win - 1;
            float val = ba[o];
            if (ts >= 0 && ts < TT)
                val += g_B[((size_t)(n*C4V + o)*TT + ts)*VV + v];
            tile[r][w] = val;
        }
        __syncthreads();
        if (tid < 225) {
#pragma unroll 4
            for (int r = 0; r < 32; r++) {
                float av[5], bv[5];
#pragma unroll
                for (int i = 0; i < 5; i++) { av[i] = tile[r][tw1*5+i]; bv[i] = tile[r][tw2*5+i]; }
#pragma unroll
                for (int i = 0; i < 5; i++)
#pragma unroll
                    for (int j = 0; j < 5; j++) acc[i][j] += av[i]*bv[j];
            }
        }
        __syncthreads();
    }
    if (tid < 225) {
        float* gp = g_Gpart + (size_t)(n*KSPLIT + ks)*W3V*W3V;
#pragma unroll
        for (int i = 0; i < 5; i++)
#pragma unroll
            for (int j = 0; j < 5; j++)
                gp[(tw1*5+i)*W3V + (tw2*5+j)] = acc[i][j];
    }
}

// ============================================================
// K3: reduce partials, scale by 1/75, softmax over w1 (per column w2)
// ============================================================
__global__ void k3_softmax()
{
    __shared__ float sG[W3V*W3V];
    int n = blockIdx.x, tid = threadIdx.x;
    for (int i = tid; i < W3V*W3V; i += blockDim.x) {
        float s = 0.f;
        for (int p = 0; p < KSPLIT; p++)
            s += g_Gpart[(size_t)(n*KSPLIT + p)*W3V*W3V + i];
        sG[i] = s * (1.0f / (float)W3V);
    }
    __syncthreads();
    if (tid < W3V) {
        float mx = -1e30f;
        for (int w1 = 0; w1 < W3V; w1++) mx = fmaxf(mx, sG[w1*W3V + tid]);
        float sum = 0.f;
        for (int w1 = 0; w1 < W3V; w1++) {
            float e = expf(sG[w1*W3V + tid] - mx);
            sG[w1*W3V + tid] = e;
            sum += e;
        }
        float inv = 1.f / sum;
        for (int w1 = 0; w1 < W3V; w1++)
            g_att[(size_t)n*W3V*W3V + w1*W3V + tid] = sG[w1*W3V + tid] * inv;
    }
}

// ============================================================
// K4: fused main path, one block per (n, 4 consecutive t)
// ============================================================
#define SM_AEFF 0
#define SM_ATT  (SM_AEFF + 3*W3V*W3V)   /* +16875 */
#define SM_WD   (SM_ATT  + W3V*W3V)     /* +5625  */
#define SM_WC   (SM_WD   + C4V*CC)      /* +1024  */
#define SM_WO   (SM_WC   + 48*CC)       /* +3072  */
#define SM_BN   (SM_WO   + COV*48)      /* +3072  */
#define SM_SLAB (SM_BN   + 128)
#define SM_D1   (SM_SLAB + CC*W3V)      /* +4800  */
#define SM_G    (SM_D1   + C4V*W3V)     /* +1200  */
#define SM_X1   (SM_G    + 48*W3V)      /* +3600  */
#define SM_TOT  (SM_X1   + C4V*W3V)     /* +1200 = 40596 floats */

__global__ void __launch_bounds__(512, 1) k4_main(
    const float* __restrict__ x,
    const float* __restrict__ A,   const float* __restrict__ PA,
    const float* __restrict__ Wd,  const float* __restrict__ bd,
    const float* __restrict__ Wc,  const float* __restrict__ bc,
    const float* __restrict__ Wo,  const float* __restrict__ bo,
    const float* __restrict__ gma, const float* __restrict__ bta,
    const float* __restrict__ mean,const float* __restrict__ var,
    float* __restrict__ out)
{
    extern __shared__ float sm[];
    int tid = threadIdx.x;
    int n  = blockIdx.x / (TT/TPB);
    int t0 = (blockIdx.x % (TT/TPB)) * TPB;

    // ---- phase A: per-block constants into SMEM ----
    for (int i = tid; i < 3*W3V*W3V; i += blockDim.x) sm[SM_AEFF+i] = A[i] + PA[i];
    for (int i = tid; i < W3V*W3V;   i += blockDim.x) sm[SM_ATT +i] = g_att[(size_t)n*W3V*W3V + i];
    for (int i = tid; i < C4V*CC;    i += blockDim.x) sm[SM_WD  +i] = Wd[i];
    for (int i = tid; i < 48*CC;     i += blockDim.x) sm[SM_WC  +i] = Wc[i];
    for (int i = tid; i < COV*48;    i += blockDim.x) sm[SM_WO  +i] = Wo[i];
    if (tid < COV) {
        float sc = gma[tid] * rsqrtf(var[tid] + 1e-5f);
        sm[SM_BN + tid]      = sc;
        sm[SM_BN + 64 + tid] = bta[tid] - mean[tid]*sc;
    }
    __syncthreads();

    for (int it = 0; it < TPB; it++) {
        int t = t0 + it;

        // ---- P1: slab[c][w] = x2[n,c,t,w] (unfold on the fly) ----
        for (int i = tid; i < CC*W3V; i += blockDim.x) {
            int c = i / W3V, w = i - c*W3V;
            int win = w / VV, v = w - win*VV;
            int ts = t + win - 1;
            sm[SM_SLAB + i] = (ts >= 0 && ts < TT)
                ? x[((size_t)(n*CC + c)*TT + ts)*VV + v] : 0.f;
        }
        __syncthreads();

        // ---- P2: d1 = conv_d(slab), g = conv(slab)  (64 rows x 75) ----
        if (tid < 480) {
            int jg = tid / 15, wg = tid - jg*15;
            int j0 = jg*2, w0 = wg*5;
            const float* Wrow0 = (j0 < C4V) ? &sm[SM_WD + j0*CC]
                                            : &sm[SM_WC + (j0 - C4V)*CC];
            const float* Wrow1 = Wrow0 + CC; // j0 even: pair never straddles WD/WC boundary
            float a0[5] = {0,0,0,0,0}, a1[5] = {0,0,0,0,0};
#pragma unroll 4
            for (int c = 0; c < CC; c++) {
                float wa = Wrow0[c], wb = Wrow1[c];
#pragma unroll
                for (int i = 0; i < 5; i++) {
                    float s = sm[SM_SLAB + c*W3V + w0 + i];
                    a0[i] += wa*s; a1[i] += wb*s;
                }
            }
            float b0 = (j0   < C4V) ? bd[j0]   : bc[j0   - C4V];
            float b1 = (j0+1 < C4V) ? bd[j0+1] : bc[j0+1 - C4V];
            int base0 = (j0   < C4V) ? (SM_D1 + j0*W3V)       : (SM_G + (j0   - C4V)*W3V);
            int base1 = (j0+1 < C4V) ? (SM_D1 + (j0+1)*W3V)   : (SM_G + (j0+1 - C4V)*W3V);
#pragma unroll
            for (int i = 0; i < 5; i++) {
                sm[base0 + w0 + i] = a0[i] + b0;
                sm[base1 + w0 + i] = a1[i] + b1;
            }
        }
        __syncthreads();

        // ---- P3: x1[c][w2] = d1 @ att + sum_k g_k @ Aeff_k  (16x75, K=300) ----
        if (tid < 240) {
            int c  = tid / 15, wg = tid - (tid/15)*15;
            int w0 = wg*5;
            float acc[5] = {0,0,0,0,0};
#pragma unroll 5
            for (int w1 = 0; w1 < W3V; w1++) {
                float d = sm[SM_D1 + c*W3V + w1];
#pragma unroll
                for (int i = 0; i < 5; i++) acc[i] += d * sm[SM_ATT + w1*W3V + w0 + i];
            }
#pragma unroll
            for (int k = 0; k < 3; k++) {
#pragma unroll 5
                for (int v = 0; v < W3V; v++) {
                    float gv = sm[SM_G + (k*C4V + c)*W3V + v];
#pragma unroll
                    for (int i = 0; i < 5; i++)
                        acc[i] += gv * sm[SM_AEFF + (k*W3V + v)*W3V + w0 + i];
                }
            }
#pragma unroll
            for (int i = 0; i < 5; i++) sm[SM_X1 + c*W3V + w0 + i] = acc[i];
        }
        __syncthreads();

        // ---- P4: out conv (1,3,1) + BN + residual + relu ----
        if (tid < 320) {
            int o = tid / 5, vg = tid - (tid/5)*5;
            int v0 = vg*5;
            float acc[5] = {0,0,0,0,0};
#pragma unroll
            for (int c = 0; c < C4V; c++) {
#pragma unroll
                for (int win = 0; win < 3; win++) {
                    float w = sm[SM_WO + o*48 + c*3 + win];
#pragma unroll
                    for (int i = 0; i < 5; i++)
                        acc[i] += w * sm[SM_X1 + c*W3V + win*VV + v0 + i];
                }
            }
            float b  = bo[o];
            float sc = sm[SM_BN + o], sh = sm[SM_BN + 64 + o];
            size_t base = ((size_t)(n*COV + o)*TT + t)*VV + v0;
#pragma unroll
            for (int i = 0; i < 5; i++) {
                float y = (acc[i] + b)*sc + sh + x[base + i];
                out[base + i] = fmaxf(y, 0.f);
            }
        }
        __syncthreads();
    }
}

// ============================================================
extern "C" void kernel_launch(void* const* d_in, const int* in_sizes, int n_in,
                              void* d_out, int out_size)
{
    (void)in_sizes; (void)n_in; (void)out_size;
    const float* x   = (const float*)d_in[0];
    const float* A   = (const float*)d_in[1];
    const float* PA  = (const float*)d_in[2];
    const float* Waw = (const float*)d_in[3];
    const float* Wab = (const float*)d_in[4];
    const float* Wdw = (const float*)d_in[5];
    const float* Wdb = (const float*)d_in[6];
    const float* Wcw = (const float*)d_in[7];
    const float* Wcb = (const float*)d_in[8];
    const float* Wow = (const float*)d_in[9];
    const float* Wob = (const float*)d_in[10];
    const float* gm  = (const float*)d_in[11];
    const float* bt  = (const float*)d_in[12];
    const float* mn  = (const float*)d_in[13];
    const float* vr  = (const float*)d_in[14];
    float* out = (float*)d_out;

    const size_t smem = SM_TOT * sizeof(float);
    cudaFuncSetAttribute(k4_main, cudaFuncAttributeMaxDynamicSharedMemorySize, (int)smem);

    k1_convA<<<dim3((TT*VV + 1023)/1024, NN), 256>>>(x, Waw);
    k2_gram <<<dim3(KSPLIT, NN), 256>>>(Wab);
    k3_softmax<<<NN, 128>>>();
    k4_main<<<NN*(TT/TPB), 512, smem>>>(x, A, PA, Wdw, Wdb, Wcw, Wcb,
                                        Wow, Wob, gm, bt, mn, vr, out);
}

// round 2
// speedup vs baseline: 1.3724x; 1.3724x over previous
#include <cuda_runtime.h>
#include <math.h>

#define NN 32
#define CC 64
#define TT 512
#define VV 25
#define C4V 16
#define W3V 75
#define COV 64
#define KSPLIT 8
#define KTOT (C4V*TT)        /* 8192 */
#define KCHUNK (KTOT/KSPLIT) /* 1024 */
#define TPB 4

// -------- device scratch (static; no runtime allocation) --------
__device__ float g_B[NN*C4V*TT*VV];          // conv_a(x) without bias
__device__ float g_Gpart[NN*KSPLIT*W3V*W3V]; // Gram partials
__device__ float g_att[NN*W3V*W3V];          // softmax(att)

// ============================================================
// K1: B[n,o,t,v] = sum_c conv_a_w[o,c] * x[n,c,t,v]
// ============================================================
__global__ void k1_convA(const float* __restrict__ x, const float* __restrict__ Wa)
{
    __shared__ float sW[C4V*CC];
    int tid = threadIdx.x;
    for (int i = tid; i < C4V*CC; i += blockDim.x) sW[i] = Wa[i];
    __syncthreads();

    int n  = blockIdx.y;
    int j0 = (blockIdx.x * blockDim.x + tid) * 4;
    if (j0 >= TT*VV) return;

    const float* xp = x + (size_t)n*CC*TT*VV + j0;
    float acc[C4V][4];
#pragma unroll
    for (int o = 0; o < C4V; o++) { acc[o][0]=acc[o][1]=acc[o][2]=acc[o][3]=0.f; }

#pragma unroll 4
    for (int c = 0; c < CC; c++) {
        float4 xv = *reinterpret_cast<const float4*>(xp + (size_t)c*TT*VV);
#pragma unroll
        for (int o = 0; o < C4V; o++) {
            float w = sW[o*CC + c];
            acc[o][0] += w*xv.x; acc[o][1] += w*xv.y;
            acc[o][2] += w*xv.z; acc[o][3] += w*xv.w;
        }
    }
    float* bp = g_B + (size_t)n*C4V*TT*VV + j0;
#pragma unroll
    for (int o = 0; o < C4V; o++) {
        float4 r = make_float4(acc[o][0], acc[o][1], acc[o][2], acc[o][3]);
        *reinterpret_cast<float4*>(bp + (size_t)o*TT*VV) = r;
    }
}

// ============================================================
// K2: Gram partials
// ============================================================
__global__ void k2_gram(const float* __restrict__ ba)
{
    __shared__ float tile[32][W3V + 1];
    int n  = blockIdx.y;
    int ks = blockIdx.x;
    int tid = threadIdx.x;
    int tw1 = tid / 15, tw2 = tid % 15;

    float acc[5][5];
#pragma unroll
    for (int i = 0; i < 5; i++)
#pragma unroll
        for (int j = 0; j < 5; j++) acc[i][j] = 0.f;

    int k0 = ks * KCHUNK;
    for (int kt = 0; kt < KCHUNK; kt += 32) {
        for (int i = tid; i < 32*W3V; i += blockDim.x) {
            int r = i / W3V, w = i - r*W3V;
            int k = k0 + kt + r;
            int o = k >> 9, t = k & 511;
            int win = w / VV, v = w - win*VV;
            int ts = t + win - 1;
            float val = ba[o];
            if (ts >= 0 && ts < TT)
                val += g_B[((size_t)(n*C4V + o)*TT + ts)*VV + v];
            tile[r][w] = val;
        }
        __syncthreads();
        if (tid < 225) {
#pragma unroll 4
            for (int r = 0; r < 32; r++) {
                float av[5], bv[5];
#pragma unroll
                for (int i = 0; i < 5; i++) { av[i] = tile[r][tw1*5+i]; bv[i] = tile[r][tw2*5+i]; }
#pragma unroll
                for (int i = 0; i < 5; i++)
#pragma unroll
                    for (int j = 0; j < 5; j++) acc[i][j] += av[i]*bv[j];
            }
        }
        __syncthreads();
    }
    if (tid < 225) {
        float* gp = g_Gpart + (size_t)(n*KSPLIT + ks)*W3V*W3V;
#pragma unroll
        for (int i = 0; i < 5; i++)
#pragma unroll
            for (int j = 0; j < 5; j++)
                gp[(tw1*5+i)*W3V + (tw2*5+j)] = acc[i][j];
    }
}

// ============================================================
// K3: reduce + softmax over w1
// ============================================================
__global__ void k3_softmax()
{
    __shared__ float sG[W3V*W3V];
    int n = blockIdx.x, tid = threadIdx.x;
    for (int i = tid; i < W3V*W3V; i += blockDim.x) {
        float s = 0.f;
        for (int p = 0; p < KSPLIT; p++)
            s += g_Gpart[(size_t)(n*KSPLIT + p)*W3V*W3V + i];
        sG[i] = s * (1.0f / (float)W3V);
    }
    __syncthreads();
    if (tid < W3V) {
        float mx = -1e30f;
        for (int w1 = 0; w1 < W3V; w1++) mx = fmaxf(mx, sG[w1*W3V + tid]);
        float sum = 0.f;
        for (int w1 = 0; w1 < W3V; w1++) {
            float e = expf(sG[w1*W3V + tid] - mx);
            sG[w1*W3V + tid] = e;
            sum += e;
        }
        float inv = 1.f / sum;
        for (int w1 = 0; w1 < W3V; w1++)
            g_att[(size_t)n*W3V*W3V + w1*W3V + tid] = sG[w1*W3V + tid] * inv;
    }
}

// ============================================================
// K4 v2: fused main path, one block per (n, 4 t), batched-t GEMMs
//   P2: L[64 x 300] = W[64x64] * S[64 x 300]   (register 8x5 tiles)
//   P3: X1[64 x 75] = L[64 x 300] * R[300 x 75] (4x5 tiles, K-split 2)
//   P4: out conv (1,3,1) + BN + residual + relu
// SMEM float offsets:
// ============================================================
#define SM_R   0            /* [300][75]  att rows 0-74, Aeff rows 75-299 */
#define SM_LT  22500        /* L^T [300][64] */
#define SM_WT  41700        /* W^T [64c][64j] (j<16: conv_d, j>=16: conv) */
#define SM_WO  45796        /* [64][48] */
#define SM_S   48868        /* union: S chunk [16][300]  /  X1 [64][75] */
#define SM_BN  53668        /* 64 scale + 64 shift */
#define SM_TOT 53796        /* floats -> 215184 bytes */

__global__ void __launch_bounds__(512, 1) k4_main(
    const float* __restrict__ x,
    const float* __restrict__ A,   const float* __restrict__ PA,
    const float* __restrict__ Wd,  const float* __restrict__ bd,
    const float* __restrict__ Wc,  const float* __restrict__ bc,
    const float* __restrict__ Wo,  const float* __restrict__ bo,
    const float* __restrict__ gma, const float* __restrict__ bta,
    const float* __restrict__ mean,const float* __restrict__ var,
    float* __restrict__ out)
{
    extern __shared__ float sm[];
    int tid = threadIdx.x;
    int n  = blockIdx.x >> 7;           // 128 blocks per n
    int t0 = (blockIdx.x & 127) << 2;   // 4 t per block

    // ---- phase A: per-block constants ----
    const float* attn = g_att + (size_t)n*W3V*W3V;
    for (int i = tid; i < 22500; i += 512)
        sm[SM_R + i] = (i < 5625) ? attn[i] : (A[i-5625] + PA[i-5625]);
    for (int i = tid; i < 4096; i += 512) {
        int c = i >> 6, j = i & 63;
        sm[SM_WT + i] = (j < C4V) ? Wd[j*CC + c] : Wc[(j-C4V)*CC + c];
    }
    for (int i = tid; i < 3072; i += 512) sm[SM_WO + i] = Wo[i];
    if (tid < COV) {
        float sc = gma[tid] * rsqrtf(var[tid] + 1e-5f);
        sm[SM_BN + tid]      = sc;
        sm[SM_BN + 64 + tid] = (bo[tid] - mean[tid])*sc + bta[tid];
    }

    // ---- P2: 64x300x64 GEMM, 8x5 tiles, 480 threads ----
    const bool act2 = tid < 480;
    int jt = 0, itw0 = 0, it2 = 0, w20 = 0;
    float acc2[8][5];
    if (act2) {
        jt = tid / 60;
        itw0 = (tid % 60) * 5;
        it2 = itw0 / 75;
        w20 = itw0 - it2*75;
#pragma unroll
        for (int a = 0; a < 8; a++)
#pragma unroll
            for (int b = 0; b < 5; b++) acc2[a][b] = 0.f;
    }
    __syncthreads();

    for (int cc = 0; cc < 4; cc++) {
        // load S chunk: rows r = 0..15 (global c = cc*16+r), cols (it,w)
        for (int i = tid; i < 4800; i += 512) {
            int r = i / 300, rem = i - r*300;
            int it = rem / 75, w = rem - it*75;
            int win = w / VV, v = w - win*VV;
            int ts = t0 + it + win - 1;
            float val = 0.f;
            if (ts >= 0 && ts < TT)
                val = x[((size_t)(n*CC + cc*16 + r)*TT + ts)*VV + v];
            sm[SM_S + i] = val;
        }
        __syncthreads();
        if (act2) {
            const float* wbase = &sm[SM_WT + (cc*16)*64 + jt*8];
            const float* sbase = &sm[SM_S + itw0];
#pragma unroll 4
            for (int cl = 0; cl < 16; cl++) {
                float4 wa = *reinterpret_cast<const float4*>(wbase + cl*64);
                float4 wb = *reinterpret_cast<const float4*>(wbase + cl*64 + 4);
                float wv[8] = {wa.x, wa.y, wa.z, wa.w, wb.x, wb.y, wb.z, wb.w};
                float sv[5];
#pragma unroll
                for (int i = 0; i < 5; i++) sv[i] = sbase[cl*300 + i];
#pragma unroll
                for (int jj = 0; jj < 8; jj++)
#pragma unroll
                    for (int i = 0; i < 5; i++) acc2[jj][i] += wv[jj]*sv[i];
            }
        }
        __syncthreads();
    }

    // write L^T [k][m] with bias; rows 0-15 -> d1 (k=w), rows 16-63 -> g (k=75+kk*75+w)
    if (act2) {
#pragma unroll
        for (int jj = 0; jj < 8; jj++) {
            int j = jt*8 + jj;
            int m, kbase; float bias;
            if (j < C4V) { m = it2*16 + j; kbase = 0; bias = bd[j]; }
            else {
                int jg = j - C4V;
                m = it2*16 + (jg & 15);
                kbase = 75 + (jg >> 4)*75;
                bias = bc[jg];
            }
#pragma unroll
            for (int i = 0; i < 5; i++)
                sm[SM_LT + (kbase + w20 + i)*64 + m] = acc2[jj][i] + bias;
        }
    }
    __syncthreads();

    // ---- P3: 64x75x300 GEMM, 4x5 tiles, K-split 2, 480 threads ----
    const bool act3 = tid < 480;
    int kh = 0, mt = 0, nt3 = 0;
    float acc3[4][5];
    if (act3) {
        kh = tid / 240;
        int r = tid - kh*240;
        mt = r / 15; nt3 = r - mt*15;
#pragma unroll
        for (int a = 0; a < 4; a++)
#pragma unroll
            for (int b = 0; b < 5; b++) acc3[a][b] = 0.f;

        const float4* LTp = reinterpret_cast<const float4*>(&sm[SM_LT]) + mt;
        const float*  Rp  = &sm[SM_R + nt3*5];
        int k0 = kh*150;
        LTp += (size_t)k0*16;
        Rp  += (size_t)k0*75;
#pragma unroll 2
        for (int k = 0; k < 150; k++) {
            float4 a = LTp[k*16];
            float r0 = Rp[k*75+0], r1 = Rp[k*75+1], r2 = Rp[k*75+2],
                  r3 = Rp[k*75+3], r4 = Rp[k*75+4];
            acc3[0][0] += a.x*r0; acc3[0][1] += a.x*r1; acc3[0][2] += a.x*r2;
            acc3[0][3] += a.x*r3; acc3[0][4] += a.x*r4;
            acc3[1][0] += a.y*r0; acc3[1][1] += a.y*r1; acc3[1][2] += a.y*r2;
            acc3[1][3] += a.y*r3; acc3[1][4] += a.y*r4;
            acc3[2][0] += a.z*r0; acc3[2][1] += a.z*r1; acc3[2][2] += a.z*r2;
            acc3[2][3] += a.z*r3; acc3[2][4] += a.z*r4;
            acc3[3][0] += a.w*r0; acc3[3][1] += a.w*r1; acc3[3][2] += a.w*r2;
            acc3[3][3] += a.w*r3; acc3[3][4] += a.w*r4;
        }
    }
    // reduce K halves through X1 (SM_S union; S is dead now)
    if (act3 && kh == 1) {
#pragma unroll
        for (int rr = 0; rr < 4; rr++)
#pragma unroll
            for (int i = 0; i < 5; i++)
                sm[SM_S + (mt*4+rr)*75 + nt3*5 + i] = acc3[rr][i];
    }
    __syncthreads();
    if (act3 && kh == 0) {
#pragma unroll
        for (int rr = 0; rr < 4; rr++)
#pragma unroll
            for (int i = 0; i < 5; i++)
                sm[SM_S + (mt*4+rr)*75 + nt3*5 + i] += acc3[rr][i];
    }
    __syncthreads();

    // ---- P4: out conv (1,3,1) + BN + residual + relu ----
    if (tid < 320) {
        int o = tid / 5, v0 = (tid - (tid/5)*5)*5;
        float sc = sm[SM_BN + o], sh = sm[SM_BN + 64 + o];
        const float* wo = &sm[SM_WO + o*48];
#pragma unroll
        for (int it = 0; it < 4; it++) {
            float acc[5] = {0,0,0,0,0};
#pragma unroll
            for (int c = 0; c < C4V; c++) {
#pragma unroll
                for (int win = 0; win < 3; win++) {
                    float w = wo[c*3 + win];
                    const float* xp = &sm[SM_S + (it*16+c)*75 + win*VV + v0];
#pragma unroll
                    for (int i = 0; i < 5; i++) acc[i] += w*xp[i];
                }
            }
            size_t base = ((size_t)(n*COV + o)*TT + (t0+it))*VV + v0;
#pragma unroll
            for (int i = 0; i < 5; i++)
                out[base + i] = fmaxf(acc[i]*sc + sh + x[base + i], 0.f);
        }
    }
}

// ============================================================
extern "C" void kernel_launch(void* const* d_in, const int* in_sizes, int n_in,
                              void* d_out, int out_size)
{
    (void)in_sizes; (void)n_in; (void)out_size;
    const float* x   = (const float*)d_in[0];
    const float* A   = (const float*)d_in[1];
    const float* PA  = (const float*)d_in[2];
    const float* Waw = (const float*)d_in[3];
    const float* Wab = (const float*)d_in[4];
    const float* Wdw = (const float*)d_in[5];
    const float* Wdb = (const float*)d_in[6];
    const float* Wcw = (const float*)d_in[7];
    const float* Wcb = (const float*)d_in[8];
    const float* Wow = (const float*)d_in[9];
    const float* Wob = (const float*)d_in[10];
    const float* gm  = (const float*)d_in[11];
    const float* bt  = (const float*)d_in[12];
    const float* mn  = (const float*)d_in[13];
    const float* vr  = (const float*)d_in[14];
    float* out = (float*)d_out;

    const size_t smem = SM_TOT * sizeof(float);
    cudaFuncSetAttribute(k4_main, cudaFuncAttributeMaxDynamicSharedMemorySize, (int)smem);

    k1_convA<<<dim3((TT*VV + 1023)/1024, NN), 256>>>(x, Waw);
    k2_gram <<<dim3(KSPLIT, NN), 256>>>(Wab);
    k3_softmax<<<NN, 128>>>();
    k4_main<<<NN*(TT/TPB), 512, smem>>>(x, A, PA, Wdw, Wdb, Wcw, Wcb,
                                        Wow, Wob, gm, bt, mn, vr, out);
}

// round 3
// speedup vs baseline: 2.4021x; 1.7503x over previous
#include <cuda_runtime.h>
#include <math.h>

#define NN 32
#define CC 64
#define TT 512
#define VV 25
#define C4V 16
#define W3V 75
#define COV 64
#define KSPLIT 8
#define KTOT (C4V*TT)        /* 8192 */
#define KCHUNK (KTOT/KSPLIT) /* 1024 */
#define TVTOT (TT*VV)        /* 12800 */

// -------- device scratch --------
__device__ float g_B[NN*C4V*TT*VV];          // conv_a(x), ch-major, NO bias
__device__ float g_L[(size_t)NN*TVTOT*64];   // [n][tv][ch] ch = [d 0-15 | g0 | g1 | g2], WITH bias
__device__ float g_Gpart[NN*KSPLIT*W3V*W3V];
__device__ float g_att[NN*W3V*W3V];

// ============================================================
// K1: 80-channel 1x1 conv GEMM on raw x (conv commutes with unfold)
//   block: 128 tv positions x 80 channels, 320 threads (8ch x 4tv tiles)
// ============================================================
#define K1_TV 128
__global__ void __launch_bounds__(320) k1_conv80(
    const float* __restrict__ x,
    const float* __restrict__ Wa,
    const float* __restrict__ Wd, const float* __restrict__ bd,
    const float* __restrict__ Wc, const float* __restrict__ bc)
{
    extern __shared__ float sm[];
    float* sX = sm;                 // [64][128]
    float* sW = sm + 8192;          // [64c][80j]
    float* sB = sm + 8192 + 5120;   // [80]
    int tid = threadIdx.x;
    int n   = blockIdx.y;
    int tv0 = blockIdx.x * K1_TV;

    for (int i = tid; i < 5120; i += 320) {
        int c = i / 80, j = i - c*80;
        float w;
        if (j < 16)      w = Wd[j*CC + c];
        else if (j < 64) w = Wc[(j-16)*CC + c];
        else             w = Wa[(j-64)*CC + c];
        sW[i] = w;
    }
    if (tid < 80) sB[tid] = (tid < 16) ? bd[tid] : (tid < 64 ? bc[tid-16] : 0.f);

    const float* xp = x + (size_t)n*CC*TVTOT + tv0;
    for (int i = tid; i < 2048; i += 320) {
        int c = i >> 5, o = (i & 31) << 2;
        *reinterpret_cast<float4*>(&sX[c*128 + o]) =
            *reinterpret_cast<const float4*>(xp + (size_t)c*TVTOT + o);
    }
    __syncthreads();

    int jt = tid / 32;             // 0..9 (8 channels each)
    int tq = (tid & 31) << 2;      // local tv, 4 wide
    float acc[8][4];
#pragma unroll
    for (int a = 0; a < 8; a++)
#pragma unroll
        for (int b = 0; b < 4; b++) acc[a][b] = 0.f;

#pragma unroll 4
    for (int c = 0; c < 64; c++) {
        float4 xv = *reinterpret_cast<const float4*>(&sX[c*128 + tq]);
        float4 wa = *reinterpret_cast<const float4*>(&sW[c*80 + jt*8]);
        float4 wb = *reinterpret_cast<const float4*>(&sW[c*80 + jt*8 + 4]);
        float wv[8] = {wa.x, wa.y, wa.z, wa.w, wb.x, wb.y, wb.z, wb.w};
        float sv[4] = {xv.x, xv.y, xv.z, xv.w};
#pragma unroll
        for (int jj = 0; jj < 8; jj++)
#pragma unroll
            for (int t4 = 0; t4 < 4; t4++) acc[jj][t4] += wv[jj]*sv[t4];
    }

    int j0 = jt*8;
    if (j0 < 64) {
        // g_L [n][tv][ch], with bias
        float b[8];
#pragma unroll
        for (int jj = 0; jj < 8; jj++) b[jj] = sB[j0+jj];
        float* gl = g_L + ((size_t)n*TVTOT + tv0 + tq)*64 + j0;
#pragma unroll
        for (int t4 = 0; t4 < 4; t4++) {
            float4 r0 = make_float4(acc[0][t4]+b[0], acc[1][t4]+b[1],
                                    acc[2][t4]+b[2], acc[3][t4]+b[3]);
            float4 r1 = make_float4(acc[4][t4]+b[4], acc[5][t4]+b[5],
                                    acc[6][t4]+b[6], acc[7][t4]+b[7]);
            *reinterpret_cast<float4*>(gl + (size_t)t4*64)     = r0;
            *reinterpret_cast<float4*>(gl + (size_t)t4*64 + 4) = r1;
        }
    } else {
        // conv_a -> g_B ch-major, NO bias (K2 adds it)
#pragma unroll
        for (int jj = 0; jj < 8; jj++) {
            int o = j0 - 64 + jj;
            float4 r = make_float4(acc[jj][0], acc[jj][1], acc[jj][2], acc[jj][3]);
            *reinterpret_cast<float4*>(g_B + (size_t)(n*C4V + o)*TVTOT + tv0 + tq) = r;
        }
    }
}

// ============================================================
// K2: Gram partials (unchanged)
// ============================================================
__global__ void k2_gram(const float* __restrict__ ba)
{
    __shared__ float tile[32][W3V + 1];
    int n  = blockIdx.y;
    int ks = blockIdx.x;
    int tid = threadIdx.x;
    int tw1 = tid / 15, tw2 = tid % 15;

    float acc[5][5];
#pragma unroll
    for (int i = 0; i < 5; i++)
#pragma unroll
        for (int j = 0; j < 5; j++) acc[i][j] = 0.f;

    int k0 = ks * KCHUNK;
    for (int kt = 0; kt < KCHUNK; kt += 32) {
        for (int i = tid; i < 32*W3V; i += blockDim.x) {
            int r = i / W3V, w = i - r*W3V;
            int k = k0 + kt + r;
            int o = k >> 9, t = k & 511;
            int win = w / VV, v = w - win*VV;
            int ts = t + win - 1;
            float val = ba[o];
            if (ts >= 0 && ts < TT)
                val += g_B[((size_t)(n*C4V + o)*TT + ts)*VV + v];
            tile[r][w] = val;
        }
        __syncthreads();
        if (tid < 225) {
#pragma unroll 4
            for (int r = 0; r < 32; r++) {
                float av[5], bv[5];
#pragma unroll
                for (int i = 0; i < 5; i++) { av[i] = tile[r][tw1*5+i]; bv[i] = tile[r][tw2*5+i]; }
#pragma unroll
                for (int i = 0; i < 5; i++)
#pragma unroll
                    for (int j = 0; j < 5; j++) acc[i][j] += av[i]*bv[j];
            }
        }
        __syncthreads();
    }
    if (tid < 225) {
        float* gp = g_Gpart + (size_t)(n*KSPLIT + ks)*W3V*W3V;
#pragma unroll
        for (int i = 0; i < 5; i++)
#pragma unroll
            for (int j = 0; j < 5; j++)
                gp[(tw1*5+i)*W3V + (tw2*5+j)] = acc[i][j];
    }
}

// ============================================================
// K3: reduce + softmax over w1 (unchanged)
// ============================================================
__global__ void k3_softmax()
{
    __shared__ float sG[W3V*W3V];
    int n = blockIdx.x, tid = threadIdx.x;
    for (int i = tid; i < W3V*W3V; i += blockDim.x) {
        float s = 0.f;
        for (int p = 0; p < KSPLIT; p++)
            s += g_Gpart[(size_t)(n*KSPLIT + p)*W3V*W3V + i];
        sG[i] = s * (1.0f / (float)W3V);
    }
    __syncthreads();
    if (tid < W3V) {
        float mx = -1e30f;
        for (int w1 = 0; w1 < W3V; w1++) mx = fmaxf(mx, sG[w1*W3V + tid]);
        float sum = 0.f;
        for (int w1 = 0; w1 < W3V; w1++) {
            float e = expf(sG[w1*W3V + tid] - mx);
            sG[w1*W3V + tid] = e;
            sum += e;
        }
        float inv = 1.f / sum;
        for (int w1 = 0; w1 < W3V; w1++)
            g_att[(size_t)n*W3V*W3V + w1*W3V + tid] = sG[w1*W3V + tid] * inv;
    }
}

// ============================================================
// K4 v3: per (n, 8 t): X1[128][75] = sum of 4 chunks LT^T x R,
// accumulated in registers; then (1,3,1) out conv + BN + res + relu.
// ============================================================
#define SM4_R    0      /* 5632 (75x75, pad) */
#define SM4_LT   5632   /* 9600 = LT[75][128]; later X1[128][75] */
#define SM4_WOT  15232  /* 3072 = WoT[48][64] */
#define SM4_BN   18304  /* 128 */
#define SM4_BIAS 18432  /* 64 */
#define SM4_TOT  18496  /* floats = 73984 B */

__global__ void __launch_bounds__(512, 2) k4_main(
    const float* __restrict__ x,
    const float* __restrict__ A,   const float* __restrict__ PA,
    const float* __restrict__ bd,  const float* __restrict__ bc,
    const float* __restrict__ Wo,  const float* __restrict__ bo,
    const float* __restrict__ gma, const float* __restrict__ bta,
    const float* __restrict__ mean,const float* __restrict__ var,
    float* __restrict__ out)
{
    extern __shared__ float sm[];
    int tid = threadIdx.x;
    int n  = blockIdx.x >> 6;
    int t0 = (blockIdx.x & 63) << 3;   // 8 t per block

    // once-per-block constants
    for (int i = tid; i < 3072; i += 512) {
        int kc = i >> 6, o = i & 63;
        sm[SM4_WOT + i] = Wo[o*48 + kc];
    }
    if (tid < 64) {
        float sc = gma[tid] * rsqrtf(var[tid] + 1e-5f);
        sm[SM4_BN + tid]      = sc;
        sm[SM4_BN + 64 + tid] = (bo[tid] - mean[tid])*sc + bta[tid];
        sm[SM4_BIAS + tid]    = (tid < 16) ? bd[tid] : bc[tid-16];
    }

    const int mt = tid / 15;   // used when tid<480
    const int nt = tid % 15;
    float acc[4][5];
#pragma unroll
    for (int a = 0; a < 4; a++)
#pragma unroll
        for (int b = 0; b < 5; b++) acc[a][b] = 0.f;

    const float* gl = g_L + (size_t)n*TVTOT*64;

    for (int kk = 0; kk < 4; kk++) {
        __syncthreads();   // constants ready (kk=0) / previous compute done
        // R chunk [75][75]
        if (kk == 0) {
            const float* ap = g_att + (size_t)n*5625;
            for (int i = tid; i < 5625; i += 512) sm[SM4_R + i] = ap[i];
        } else {
            const float* a0 = A  + (size_t)(kk-1)*5625;
            const float* p0 = PA + (size_t)(kk-1)*5625;
            for (int i = tid; i < 5625; i += 512) sm[SM4_R + i] = a0[i] + p0[i];
        }
        // LT chunk gather: LT[k=(win,v)][m=(it,c)] from g_L (padding -> bias)
        for (int i = tid; i < 2400; i += 512) {
            int seg = i >> 2, q = (i & 3) << 2;
            int k  = seg >> 3, it = seg & 7;
            int win = (k*41) >> 10;          // k/25 for k<75
            int v   = k - win*25;
            int ts  = t0 + it + win - 1;
            float4 val;
            if ((unsigned)ts < TT)
                val = *reinterpret_cast<const float4*>(gl + ((size_t)(ts*25 + v) << 6) + kk*16 + q);
            else
                val = *reinterpret_cast<const float4*>(&sm[SM4_BIAS + kk*16 + q]);
            *reinterpret_cast<float4*>(&sm[SM4_LT + k*128 + it*16 + q]) = val;
        }
        __syncthreads();
        // chunk GEMM: acc[m 4][w2 5] += sum_k LT[k][m]*R[k][w2]
        if (tid < 480) {
            const float4* lt = reinterpret_cast<const float4*>(&sm[SM4_LT]) + mt;
            const float*  rp = &sm[SM4_R + nt*5];
#pragma unroll 5
            for (int k = 0; k < 75; k++) {
                float4 a = lt[k*32];
                float r0 = rp[k*75+0], r1 = rp[k*75+1], r2 = rp[k*75+2],
                      r3 = rp[k*75+3], r4 = rp[k*75+4];
                acc[0][0] += a.x*r0; acc[0][1] += a.x*r1; acc[0][2] += a.x*r2;
                acc[0][3] += a.x*r3; acc[0][4] += a.x*r4;
                acc[1][0] += a.y*r0; acc[1][1] += a.y*r1; acc[1][2] += a.y*r2;
                acc[1][3] += a.y*r3; acc[1][4] += a.y*r4;
                acc[2][0] += a.z*r0; acc[2][1] += a.z*r1; acc[2][2] += a.z*r2;
                acc[2][3] += a.z*r3; acc[2][4] += a.z*r4;
                acc[3][0] += a.w*r0; acc[3][1] += a.w*r1; acc[3][2] += a.w*r2;
                acc[3][3] += a.w*r3; acc[3][4] += a.w*r4;
            }
        }
    }
    __syncthreads();
    // X1 [m=(it*16+c)][75] overwrites LT region
    if (tid < 480) {
#pragma unroll
        for (int rr = 0; rr < 4; rr++)
#pragma unroll
            for (int i = 0; i < 5; i++)
                sm[SM4_LT + (mt*4+rr)*75 + nt*5 + i] = acc[rr][i];
    }
    __syncthreads();

    // P4: out conv (1,3,1) + BN + residual + relu
    if (tid < 320) {
        int it = tid / 40;
        int r  = tid - it*40;
        int ot = (r/5)*8, v0 = (r - (r/5)*5)*5;
        float po[8][5];
#pragma unroll
        for (int a = 0; a < 8; a++)
#pragma unroll
            for (int b = 0; b < 5; b++) po[a][b] = 0.f;
        const float* x1b = &sm[SM4_LT + it*16*75];
#pragma unroll
        for (int c = 0; c < 16; c++) {
#pragma unroll
            for (int win = 0; win < 3; win++) {
                int kc = c*3 + win;
                float4 wA = *reinterpret_cast<const float4*>(&sm[SM4_WOT + kc*64 + ot]);
                float4 wB = *reinterpret_cast<const float4*>(&sm[SM4_WOT + kc*64 + ot + 4]);
                float wv[8] = {wA.x, wA.y, wA.z, wA.w, wB.x, wB.y, wB.z, wB.w};
                float xv[5];
#pragma unroll
                for (int i = 0; i < 5; i++) xv[i] = x1b[c*75 + win*25 + v0 + i];
#pragma unroll
                for (int oo = 0; oo < 8; oo++)
#pragma unroll
                    for (int i = 0; i < 5; i++) po[oo][i] += wv[oo]*xv[i];
            }
        }
#pragma unroll
        for (int oo = 0; oo < 8; oo++) {
            int o = ot + oo;
            float sc = sm[SM4_BN + o], sh = sm[SM4_BN + 64 + o];
            size_t base = ((size_t)(n*COV + o)*TT + (t0 + it))*VV + v0;
#pragma unroll
            for (int i = 0; i < 5; i++)
                out[base + i] = fmaxf(po[oo][i]*sc + sh + x[base + i], 0.f);
        }
    }
}

// ============================================================
extern "C" void kernel_launch(void* const* d_in, const int* in_sizes, int n_in,
                              void* d_out, int out_size)
{
    (void)in_sizes; (void)n_in; (void)out_size;
    const float* x   = (const float*)d_in[0];
    const float* A   = (const float*)d_in[1];
    const float* PA  = (const float*)d_in[2];
    const float* Waw = (const float*)d_in[3];
    const float* Wab = (const float*)d_in[4];
    const float* Wdw = (const float*)d_in[5];
    const float* Wdb = (const float*)d_in[6];
    const float* Wcw = (const float*)d_in[7];
    const float* Wcb = (const float*)d_in[8];
    const float* Wow = (const float*)d_in[9];
    const float* Wob = (const float*)d_in[10];
    const float* gm  = (const float*)d_in[11];
    const float* bt  = (const float*)d_in[12];
    const float* mn  = (const float*)d_in[13];
    const float* vr  = (const float*)d_in[14];
    float* out = (float*)d_out;

    const size_t smem1 = (8192 + 5120 + 80) * sizeof(float);
    const size_t smem4 = SM4_TOT * sizeof(float);
    cudaFuncSetAttribute(k1_conv80, cudaFuncAttributeMaxDynamicSharedMemorySize, (int)smem1);
    cudaFuncSetAttribute(k4_main,   cudaFuncAttributeMaxDynamicSharedMemorySize, (int)smem4);

    k1_conv80<<<dim3(TVTOT/K1_TV, NN), 320, smem1>>>(x, Waw, Wdw, Wdb, Wcw, Wcb);
    k2_gram  <<<dim3(KSPLIT, NN), 256>>>(Wab);
    k3_softmax<<<NN, 128>>>();
    k4_main  <<<NN*(TT/8), 512, smem4>>>(x, A, PA, Wdb, Wcb,
                                         Wow, Wob, gm, bt, mn, vr, out);
}